// round 12
// baseline (speedup 1.0000x reference)
#include <cuda_runtime.h>
#include <cstdint>

#define Bn   64
#define Sn   1024
#define Dn   1024
#define NT   34      // tags incl BOS
#define NA   33      // active states (BOS column dead)
#define BOSI 33

// -------- scratch (static device allocations) --------
__device__ float  g_exp_proj[(size_t)Bn * NA * Sn];  // [b][j][t] exp(proj)
__device__ float  g_pm[Bn][NA];                      // forward p at mid
__device__ float  g_vm[Bn][NA];                      // backward v at mid
__device__ int    g_cntf[Bn], g_cntb[Bn];
__device__ float  g_score[Bn];

// ============================ GEMM: scalar FFMA, 4 rows/thread ============================
// 256 CTAs x 64 threads, 4 rows/thread (stride 64), KT=4.
// W double-buffered in smem (reg-staged, 1 sync/tile); A prefetched in regs.
// Each broadcast W value now feeds 4 FFMAs -> FFMA-pipe bound, not L1-bound.
#define KT4 4

// one k-step: W row kk from Wt[cur], 4 rows x 33 cols
#define GU4(A0, A1, A2, A3, KK) do{                                          \
    const float4* wr_ = (const float4*)(&Wt[cur][KK][0]);                    \
    _Pragma("unroll")                                                        \
    for (int q = 0; q < 8; q++){                                             \
        float4 w_ = wr_[q];                                                  \
        acc0[4*q+0] += (A0)*w_.x; acc0[4*q+1] += (A0)*w_.y;                  \
        acc0[4*q+2] += (A0)*w_.z; acc0[4*q+3] += (A0)*w_.w;                  \
        acc1[4*q+0] += (A1)*w_.x; acc1[4*q+1] += (A1)*w_.y;                  \
        acc1[4*q+2] += (A1)*w_.z; acc1[4*q+3] += (A1)*w_.w;                  \
        acc2[4*q+0] += (A2)*w_.x; acc2[4*q+1] += (A2)*w_.y;                  \
        acc2[4*q+2] += (A2)*w_.z; acc2[4*q+3] += (A2)*w_.w;                  \
        acc3[4*q+0] += (A3)*w_.x; acc3[4*q+1] += (A3)*w_.y;                  \
        acc3[4*q+2] += (A3)*w_.z; acc3[4*q+3] += (A3)*w_.w;                  \
    }                                                                        \
    float wl_ = Wt[cur][KK][32];                                             \
    acc0[32] += (A0)*wl_; acc1[32] += (A1)*wl_;                              \
    acc2[32] += (A2)*wl_; acc3[32] += (A3)*wl_;                              \
} while(0)

__global__ __launch_bounds__(64, 4)
void gemm_kernel(const float* __restrict__ em, const float* __restrict__ W,
                 const float* __restrict__ bias, float* __restrict__ out)
{
    __shared__ __align__(16) float Wt[2][KT4][36];
    __shared__ float s_bias[NA];
    __shared__ float s_out[64 * NA];

    const int tid = threadIdx.x;
    const int row0 = blockIdx.x * 256 + tid;      // rows: row0 + 64*r, r=0..3

    if (tid < NA) s_bias[tid] = bias[tid];

    float acc0[NA], acc1[NA], acc2[NA], acc3[NA];
    #pragma unroll
    for (int j = 0; j < NA; j++){ acc0[j]=0.f; acc1[j]=0.f; acc2[j]=0.f; acc3[j]=0.f; }

    const float4* ar0 = (const float4*)(em + (size_t)(row0)       * Dn);
    const float4* ar1 = (const float4*)(em + (size_t)(row0 + 64)  * Dn);
    const float4* ar2 = (const float4*)(em + (size_t)(row0 + 128) * Dn);
    const float4* ar3 = (const float4*)(em + (size_t)(row0 + 192) * Dn);

    // prologue: W tile 0 -> Wt[0]; A tile 0 -> abuf
    {
        #pragma unroll
        for (int q = 0; q < 3; q++){
            int i = tid + 64*q;                   // 0..191, need < 144
            if (i < KT4*36){
                int kk = i / 36, j = i - kk*36;
                (&Wt[0][0][0])[i] = (j < NA) ? W[(size_t)kk * NT + j] : 0.f;
            }
        }
    }
    float4 ab0 = ar0[0], ab1 = ar1[0], ab2 = ar2[0], ab3 = ar3[0];
    __syncthreads();

    #pragma unroll 1
    for (int kt = 0; kt < Dn/KT4; kt++){
        const int cur = kt & 1, nxt = cur ^ 1;
        const bool more = (kt < Dn/KT4 - 1);

        // prefetch next W tile into regs, next A into regs
        float wreg0 = 0.f, wreg1 = 0.f, wreg2 = 0.f;
        float4 an0, an1, an2, an3;
        if (more){
            const float* wsrc = W + (size_t)(kt+1) * KT4 * NT;
            {
                int i = tid;
                int kk = i / 36, j = i - kk*36;
                wreg0 = (j < NA) ? wsrc[(size_t)kk * NT + j] : 0.f;
            }
            {
                int i = tid + 64;
                int kk = i / 36, j = i - kk*36;
                wreg1 = (j < NA) ? wsrc[(size_t)kk * NT + j] : 0.f;
            }
            if (tid + 128 < KT4*36){
                int i = tid + 128;
                int kk = i / 36, j = i - kk*36;
                wreg2 = (j < NA) ? wsrc[(size_t)kk * NT + j] : 0.f;
            }
            an0 = ar0[kt+1]; an1 = ar1[kt+1]; an2 = ar2[kt+1]; an3 = ar3[kt+1];
        }

        // compute tile kt
        GU4(ab0.x, ab1.x, ab2.x, ab3.x, 0);
        GU4(ab0.y, ab1.y, ab2.y, ab3.y, 1);
        GU4(ab0.z, ab1.z, ab2.z, ab3.z, 2);
        GU4(ab0.w, ab1.w, ab2.w, ab3.w, 3);

        if (more){
            (&Wt[nxt][0][0])[tid]       = wreg0;
            (&Wt[nxt][0][0])[tid + 64]  = wreg1;
            if (tid + 128 < KT4*36) (&Wt[nxt][0][0])[tid + 128] = wreg2;
            __syncthreads();
            ab0 = an0; ab1 = an1; ab2 = an2; ab3 = an3;
        }
    }

    // epilogue: 4 row-chunks, each staged through smem for coalesced out stores
    #pragma unroll
    for (int r = 0; r < 4; r++){
        const float* acc = (r == 0) ? acc0 : (r == 1) ? acc1 : (r == 2) ? acc2 : acc3;
        const int row = row0 + 64*r;
        const int b = row >> 10, s = row & 1023;
        #pragma unroll
        for (int j = 0; j < NA; j++){
            float v = acc[j] + s_bias[j];
            s_out[tid * NA + j] = v;                                  // bank = tid+j mod 32: conflict-free
            g_exp_proj[((size_t)b * NA + j) * Sn + s] = __expf(v);    // coalesced per j
        }
        __syncthreads();
        float* obase = out + 1 + ((size_t)blockIdx.x * 256 + 64*r) * NA;
        #pragma unroll
        for (int q = 0; q < NA; q++)
            obase[tid + 64*q] = s_out[tid + 64*q];                    // coalesced
        __syncthreads();
    }
}

// ============================ CRF scan (fwd/bwd) + gold score, one kernel ============================
#define SCAN_BODY(PL, PH, EMJ, EM32, MK, DOT_W)                                \
{                                                                              \
    float p0v = __shfl_sync(0xffffffffu, PL, 0);                               \
    unsigned eb = __float_as_uint(p0v) >> 23;                                  \
    cnt += (int)eb - 127;                                                      \
    float scl = __uint_as_float((254u - eb) << 23);                            \
    float al0=0.f, al1=0.f, al2=0.f, al3=0.f;                                  \
    float ahh0=0.f, ahh1=0.f, ahh2=0.f, ahh3=0.f;                              \
    float wl = (DOT_W) ? (PL) * (EMJ)  : (PL);                                 \
    float wh = (DOT_W) ? (PH) * (EM32) : (PH);                                 \
    _Pragma("unroll")                                                          \
    for (int i = 0; i < 32; i += 4){                                           \
        float v0 = __shfl_sync(0xffffffffu, wl, i);                            \
        float v1 = __shfl_sync(0xffffffffu, wl, i+1);                          \
        float v2 = __shfl_sync(0xffffffffu, wl, i+2);                          \
        float v3 = __shfl_sync(0xffffffffu, wl, i+3);                          \
        al0 += v0*E_l[i];   ahh0 += v0*E_h[i];                                 \
        al1 += v1*E_l[i+1]; ahh1 += v1*E_h[i+1];                               \
        al2 += v2*E_l[i+2]; ahh2 += v2*E_h[i+2];                               \
        al3 += v3*E_l[i+3]; ahh3 += v3*E_h[i+3];                               \
    }                                                                          \
    al0 += wh*E_l[32]; ahh0 += wh*E_h[32];                                     \
    float sl = (al0+al1)+(al2+al3);                                            \
    float sh = (ahh0+ahh1)+(ahh2+ahh3);                                        \
    float nl, nh;                                                              \
    if (DOT_W){ nl = sl*scl; nh = sh*scl; }                                    \
    else      { nl = sl*((EMJ)*scl); nh = sh*((EM32)*scl); }                   \
    if ((MK) == 0.f){ nl = (PL)*scl; nh = (PH)*scl; }                          \
    PL = nl; PH = nh;                                                          \
}

__global__ __launch_bounds__(32)
void scan_kernel(const float* __restrict__ T, const float* __restrict__ mask,
                 const int* __restrict__ tags, const float* __restrict__ out)
{
    const int blk = blockIdx.x;
    const int j   = threadIdx.x;

    if (blk >= 2 * Bn){
        // ---- gold-path score for batch (blk - 2*Bn) ----
        int b = blk - 2 * Bn, lane = j;
        float partial = 0.f;
        for (int t = lane; t < Sn; t += 32){
            int   tg = tags[b*Sn + t];
            float e  = out[1 + ((size_t)b*Sn + t)*NA + tg];
            if (t == 0){
                partial += T[BOSI*NT + tg] + e;
            } else {
                int tgp = tags[b*Sn + t - 1];
                partial += (e + T[tgp*NT + tg]) * mask[b*Sn + t];
            }
        }
        #pragma unroll
        for (int o = 16; o; o >>= 1) partial += __shfl_xor_sync(0xffffffffu, partial, o);
        if (lane == 0) g_score[b] = partial;
        return;
    }

    const int b   = blk >> 1;
    const int dir = blk & 1;

    float E_l[NA], E_h[NA];
    if (dir == 0){
        #pragma unroll
        for (int i = 0; i < NA; i++){
            E_l[i] = __expf(T[i*NT + j]);
            E_h[i] = __expf(T[i*NT + 32]);
        }
    } else {
        #pragma unroll
        for (int s = 0; s < NA; s++){
            E_l[s] = __expf(T[j*NT + s]);
            E_h[s] = __expf(T[32*NT + s]);
        }
    }

    const float4* epj  = (const float4*)(g_exp_proj + ((size_t)b*NA + j ) * Sn);
    const float4* ep32 = (const float4*)(g_exp_proj + ((size_t)b*NA + 32) * Sn);
    const float4* mp4  = (const float4*)(mask + (size_t)b * Sn);

    int cnt = 0;

    if (dir == 0){
        float4 e = epj[0], e32 = ep32[0], mk = mp4[0];
        float pl = __expf(T[BOSI*NT + j])  * e.x;
        float ph = __expf(T[BOSI*NT + 32]) * e32.x;

        SCAN_BODY(pl, ph, e.y, e32.y, mk.y, 0);
        SCAN_BODY(pl, ph, e.z, e32.z, mk.z, 0);
        SCAN_BODY(pl, ph, e.w, e32.w, mk.w, 0);
        for (int gq = 1; gq < 128; gq++){
            e = epj[gq]; e32 = ep32[gq]; mk = mp4[gq];
            SCAN_BODY(pl, ph, e.x, e32.x, mk.x, 0);
            SCAN_BODY(pl, ph, e.y, e32.y, mk.y, 0);
            SCAN_BODY(pl, ph, e.z, e32.z, mk.z, 0);
            SCAN_BODY(pl, ph, e.w, e32.w, mk.w, 0);
        }
        g_pm[b][j] = pl;
        if (j == 0){ g_pm[b][32] = ph; g_cntf[b] = cnt; }
    } else {
        float vl = 1.f, vh = 1.f;
        for (int gq = 255; gq >= 128; gq--){
            float4 e = epj[gq], e32 = ep32[gq], mk = mp4[gq];
            SCAN_BODY(vl, vh, e.w, e32.w, mk.w, 1);
            SCAN_BODY(vl, vh, e.z, e32.z, mk.z, 1);
            SCAN_BODY(vl, vh, e.y, e32.y, mk.y, 1);
            SCAN_BODY(vl, vh, e.x, e32.x, mk.x, 1);
        }
        g_vm[b][j] = vl;
        if (j == 0){ g_vm[b][32] = vh; g_cntb[b] = cnt; }
    }
}

// ============================ combine + loss ============================
__global__ __launch_bounds__(32)
void loss_kernel(float* __restrict__ out)
{
    int lane = threadIdx.x;
    double v = 0.0;
    #pragma unroll
    for (int h = 0; h < 2; h++){
        int b = lane + 32*h;
        double dot = 0.0;
        #pragma unroll
        for (int i = 0; i < NA; i++) dot += (double)g_pm[b][i] * (double)g_vm[b][i];
        double part = (double)(g_cntf[b] + g_cntb[b]) * 0.6931471805599453 + log(dot);
        v += part - (double)g_score[b];
    }
    #pragma unroll
    for (int o = 16; o; o >>= 1) v += __shfl_xor_sync(0xffffffffu, v, o);
    if (lane == 0) out[0] = (float)v;
}

// ============================ launch ============================
extern "C" void kernel_launch(void* const* d_in, const int* in_sizes, int n_in,
                              void* d_out, int out_size)
{
    const float* em   = (const float*)d_in[0];   // (B,S,D)
    const int*   tags = (const int*)  d_in[1];   // (B,S)
    const float* mask = (const float*)d_in[2];   // (B,S)
    const float* W    = (const float*)d_in[3];   // (D,N)
    const float* bias = (const float*)d_in[4];   // (N,)
    const float* T    = (const float*)d_in[5];   // (N,N)
    float* out = (float*)d_out;                  // [loss, logits(B,S,33)]

    gemm_kernel <<<(Bn*Sn)/256, 64>>>(em, W, bias, out);
    scan_kernel <<<3*Bn, 32>>>(T, mask, tags, out);
    loss_kernel <<<1, 32>>>(out);
}

// round 13
// speedup vs baseline: 1.4102x; 1.4102x over previous
#include <cuda_runtime.h>
#include <cstdint>

#define Bn   64
#define Sn   1024
#define Dn   1024
#define NT   34      // tags incl BOS
#define NA   33      // active states (BOS column dead)
#define BOSI 33

// -------- scratch (static device allocations) --------
__device__ float  g_pm[Bn][NA];                      // forward p at mid
__device__ float  g_vm[Bn][NA];                      // backward v at mid
__device__ int    g_cntf[Bn], g_cntb[Bn];
__device__ float  g_score[Bn];

// ============================ GEMM: scalar FFMA, 2 rows/thread ============================
// 512 CTAs x 64 threads, 2 rows/thread (stride 64), KT=16.
// W double-buffered in smem (reg-staged, 1 sync/tile); A prefetched in regs.
// Each broadcast W float4 feeds 8 FFMAs: L1 pressure half of R11, warps 2x R12.
#define KTG 16

#define GU2(A0, A1, KK) do{                                                  \
    const float4* wr_ = (const float4*)(&Wt[cur][KK][0]);                    \
    _Pragma("unroll")                                                        \
    for (int q = 0; q < 8; q++){                                             \
        float4 w_ = wr_[q];                                                  \
        acc0[4*q+0] += (A0)*w_.x; acc0[4*q+1] += (A0)*w_.y;                  \
        acc0[4*q+2] += (A0)*w_.z; acc0[4*q+3] += (A0)*w_.w;                  \
        acc1[4*q+0] += (A1)*w_.x; acc1[4*q+1] += (A1)*w_.y;                  \
        acc1[4*q+2] += (A1)*w_.z; acc1[4*q+3] += (A1)*w_.w;                  \
    }                                                                        \
    float wl_ = Wt[cur][KK][32];                                             \
    acc0[32] += (A0)*wl_; acc1[32] += (A1)*wl_;                              \
} while(0)

__global__ __launch_bounds__(64, 4)
void gemm_kernel(const float* __restrict__ em, const float* __restrict__ W,
                 const float* __restrict__ bias, float* __restrict__ out)
{
    __shared__ __align__(16) float Wt[2][KTG][36];
    __shared__ float s_bias[NA];
    __shared__ float s_out[64 * NA];

    const int tid = threadIdx.x;
    const int row0 = blockIdx.x * 128 + tid;      // rows: row0, row0+64

    if (tid < NA) s_bias[tid] = bias[tid];

    float acc0[NA], acc1[NA];
    #pragma unroll
    for (int j = 0; j < NA; j++){ acc0[j]=0.f; acc1[j]=0.f; }

    const float4* ar0 = (const float4*)(em + (size_t)(row0)      * Dn);
    const float4* ar1 = (const float4*)(em + (size_t)(row0 + 64) * Dn);

    // prologue: W tile 0 -> Wt[0] (576 floats, 9/thread); A tile 0 -> regs
    #pragma unroll
    for (int q = 0; q < 9; q++){
        int i = tid + 64*q;
        int kk = i / 36, j = i - kk*36;
        (&Wt[0][0][0])[i] = (j < NA) ? W[(size_t)kk * NT + j] : 0.f;
    }
    float4 ab0[4], ab1[4], an0[4], an1[4];
    #pragma unroll
    for (int q = 0; q < 4; q++){ ab0[q] = ar0[q]; ab1[q] = ar1[q]; }
    __syncthreads();

    #pragma unroll 1
    for (int kt = 0; kt < Dn/KTG; kt++){
        const int cur = kt & 1, nxt = cur ^ 1;
        const bool more = (kt < Dn/KTG - 1);

        float wreg[9];
        if (more){
            const float* wsrc = W + (size_t)(kt+1) * KTG * NT;
            #pragma unroll
            for (int q = 0; q < 9; q++){
                int i = tid + 64*q;
                int kk = i / 36, j = i - kk*36;
                wreg[q] = (j < NA) ? wsrc[(size_t)kk * NT + j] : 0.f;
            }
            #pragma unroll
            for (int q = 0; q < 4; q++){
                an0[q] = ar0[(kt+1)*4 + q];
                an1[q] = ar1[(kt+1)*4 + q];
            }
        }

        #pragma unroll
        for (int kk4 = 0; kk4 < 4; kk4++){
            float4 a0 = ab0[kk4], a1 = ab1[kk4];
            GU2(a0.x, a1.x, kk4*4+0);
            GU2(a0.y, a1.y, kk4*4+1);
            GU2(a0.z, a1.z, kk4*4+2);
            GU2(a0.w, a1.w, kk4*4+3);
        }

        if (more){
            #pragma unroll
            for (int q = 0; q < 9; q++)
                (&Wt[nxt][0][0])[tid + 64*q] = wreg[q];
            __syncthreads();
            #pragma unroll
            for (int q = 0; q < 4; q++){ ab0[q] = an0[q]; ab1[q] = an1[q]; }
        }
    }

    // epilogue: 2 chunks of 64 rows, staged through smem for coalesced stores
    #pragma unroll
    for (int r = 0; r < 2; r++){
        const float* acc = (r == 0) ? acc0 : acc1;
        #pragma unroll
        for (int j = 0; j < NA; j++)
            s_out[tid * NA + j] = acc[j] + s_bias[j];
        __syncthreads();
        float* obase = out + 1 + ((size_t)blockIdx.x * 128 + 64*r) * NA;
        #pragma unroll
        for (int q = 0; q < NA; q++)
            obase[tid + 64*q] = s_out[tid + 64*q];
        __syncthreads();
    }
}

// ============================ CRF scan (fwd/bwd) + gold score ============================
// Reads logits from out[b][t][j] (coalesced across lanes), exp applied inline.
#define SCAN_BODY(PL, PH, EMJ, EM32, MK, DOT_W)                                \
{                                                                              \
    float p0v = __shfl_sync(0xffffffffu, PL, 0);                               \
    unsigned eb = __float_as_uint(p0v) >> 23;                                  \
    cnt += (int)eb - 127;                                                      \
    float scl = __uint_as_float((254u - eb) << 23);                            \
    float al0=0.f, al1=0.f, al2=0.f, al3=0.f;                                  \
    float ahh0=0.f, ahh1=0.f, ahh2=0.f, ahh3=0.f;                              \
    float wl = (DOT_W) ? (PL) * (EMJ)  : (PL);                                 \
    float wh = (DOT_W) ? (PH) * (EM32) : (PH);                                 \
    _Pragma("unroll")                                                          \
    for (int i = 0; i < 32; i += 4){                                           \
        float v0 = __shfl_sync(0xffffffffu, wl, i);                            \
        float v1 = __shfl_sync(0xffffffffu, wl, i+1);                          \
        float v2 = __shfl_sync(0xffffffffu, wl, i+2);                          \
        float v3 = __shfl_sync(0xffffffffu, wl, i+3);                          \
        al0 += v0*E_l[i];   ahh0 += v0*E_h[i];                                 \
        al1 += v1*E_l[i+1]; ahh1 += v1*E_h[i+1];                               \
        al2 += v2*E_l[i+2]; ahh2 += v2*E_h[i+2];                               \
        al3 += v3*E_l[i+3]; ahh3 += v3*E_h[i+3];                               \
    }                                                                          \
    al0 += wh*E_l[32]; ahh0 += wh*E_h[32];                                     \
    float sl = (al0+al1)+(al2+al3);                                            \
    float sh = (ahh0+ahh1)+(ahh2+ahh3);                                        \
    float nl, nh;                                                              \
    if (DOT_W){ nl = sl*scl; nh = sh*scl; }                                    \
    else      { nl = sl*((EMJ)*scl); nh = sh*((EM32)*scl); }                   \
    if ((MK) == 0.f){ nl = (PL)*scl; nh = (PH)*scl; }                          \
    PL = nl; PH = nh;                                                          \
}

__global__ __launch_bounds__(32)
void scan_kernel(const float* __restrict__ T, const float* __restrict__ mask,
                 const int* __restrict__ tags, const float* __restrict__ outp)
{
    const int blk = blockIdx.x;
    const int j   = threadIdx.x;

    if (blk >= 2 * Bn){
        // ---- gold-path score for batch (blk - 2*Bn) ----
        int b = blk - 2 * Bn, lane = j;
        float partial = 0.f;
        for (int t = lane; t < Sn; t += 32){
            int   tg = tags[b*Sn + t];
            float e  = outp[1 + ((size_t)b*Sn + t)*NA + tg];
            if (t == 0){
                partial += T[BOSI*NT + tg] + e;
            } else {
                int tgp = tags[b*Sn + t - 1];
                partial += (e + T[tgp*NT + tg]) * mask[b*Sn + t];
            }
        }
        #pragma unroll
        for (int o = 16; o; o >>= 1) partial += __shfl_xor_sync(0xffffffffu, partial, o);
        if (lane == 0) g_score[b] = partial;
        return;
    }

    const int b   = blk >> 1;
    const int dir = blk & 1;

    float E_l[NA], E_h[NA];
    if (dir == 0){
        #pragma unroll
        for (int i = 0; i < NA; i++){
            E_l[i] = __expf(T[i*NT + j]);
            E_h[i] = __expf(T[i*NT + 32]);
        }
    } else {
        #pragma unroll
        for (int s = 0; s < NA; s++){
            E_l[s] = __expf(T[j*NT + s]);
            E_h[s] = __expf(T[32*NT + s]);
        }
    }

    const float* eb_base = outp + 1 + (size_t)b * Sn * NA;   // [t][j], lane-coalesced
    const float4* mp4 = (const float4*)(mask + (size_t)b * Sn);

    int cnt = 0;

    if (dir == 0){
        // group 0 loads (t = 0..3)
        float emc[4], e3c[4];
        #pragma unroll
        for (int d = 0; d < 4; d++){
            emc[d] = eb_base[d*NA + j];
            e3c[d] = eb_base[d*NA + 32];
        }
        float4 mkc = mp4[0];

        float pl = __expf(T[BOSI*NT + j])  * __expf(emc[0]);
        float ph = __expf(T[BOSI*NT + 32]) * __expf(e3c[0]);

        float emn[4], e3n[4]; float4 mkn;
        #pragma unroll
        for (int d = 0; d < 4; d++){
            emn[d] = eb_base[(4 + d)*NA + j];
            e3n[d] = eb_base[(4 + d)*NA + 32];
        }
        mkn = mp4[1];

        // t = 1..3
        SCAN_BODY(pl, ph, __expf(emc[1]), __expf(e3c[1]), mkc.y, 0);
        SCAN_BODY(pl, ph, __expf(emc[2]), __expf(e3c[2]), mkc.z, 0);
        SCAN_BODY(pl, ph, __expf(emc[3]), __expf(e3c[3]), mkc.w, 0);

        for (int g = 1; g < 128; g++){
            #pragma unroll
            for (int d = 0; d < 4; d++){ emc[d] = emn[d]; e3c[d] = e3n[d]; }
            mkc = mkn;
            if (g + 1 < 128){
                #pragma unroll
                for (int d = 0; d < 4; d++){
                    emn[d] = eb_base[((g+1)*4 + d)*NA + j];
                    e3n[d] = eb_base[((g+1)*4 + d)*NA + 32];
                }
                mkn = mp4[g+1];
            }
            SCAN_BODY(pl, ph, __expf(emc[0]), __expf(e3c[0]), mkc.x, 0);
            SCAN_BODY(pl, ph, __expf(emc[1]), __expf(e3c[1]), mkc.y, 0);
            SCAN_BODY(pl, ph, __expf(emc[2]), __expf(e3c[2]), mkc.z, 0);
            SCAN_BODY(pl, ph, __expf(emc[3]), __expf(e3c[3]), mkc.w, 0);
        }
        g_pm[b][j] = pl;
        if (j == 0){ g_pm[b][32] = ph; g_cntf[b] = cnt; }
    } else {
        // backward: t = 1023 down to 512 (groups 255..128, d = 3..0)
        float vl = 1.f, vh = 1.f;

        float emc[4], e3c[4];
        #pragma unroll
        for (int d = 0; d < 4; d++){
            emc[d] = eb_base[(255*4 + d)*NA + j];
            e3c[d] = eb_base[(255*4 + d)*NA + 32];
        }
        float4 mkc = mp4[255];

        float emn[4], e3n[4]; float4 mkn;

        for (int g = 255; g >= 128; g--){
            if (g > 128){
                #pragma unroll
                for (int d = 0; d < 4; d++){
                    emn[d] = eb_base[((g-1)*4 + d)*NA + j];
                    e3n[d] = eb_base[((g-1)*4 + d)*NA + 32];
                }
                mkn = mp4[g-1];
            }
            SCAN_BODY(vl, vh, __expf(emc[3]), __expf(e3c[3]), mkc.w, 1);
            SCAN_BODY(vl, vh, __expf(emc[2]), __expf(e3c[2]), mkc.z, 1);
            SCAN_BODY(vl, vh, __expf(emc[1]), __expf(e3c[1]), mkc.y, 1);
            SCAN_BODY(vl, vh, __expf(emc[0]), __expf(e3c[0]), mkc.x, 1);
            #pragma unroll
            for (int d = 0; d < 4; d++){ emc[d] = emn[d]; e3c[d] = e3n[d]; }
            mkc = mkn;
        }
        g_vm[b][j] = vl;
        if (j == 0){ g_vm[b][32] = vh; g_cntb[b] = cnt; }
    }
}

// ============================ combine + loss ============================
__global__ __launch_bounds__(32)
void loss_kernel(float* __restrict__ out)
{
    int lane = threadIdx.x;
    double v = 0.0;
    #pragma unroll
    for (int h = 0; h < 2; h++){
        int b = lane + 32*h;
        double dot = 0.0;
        #pragma unroll
        for (int i = 0; i < NA; i++) dot += (double)g_pm[b][i] * (double)g_vm[b][i];
        double part = (double)(g_cntf[b] + g_cntb[b]) * 0.6931471805599453 + log(dot);
        v += part - (double)g_score[b];
    }
    #pragma unroll
    for (int o = 16; o; o >>= 1) v += __shfl_xor_sync(0xffffffffu, v, o);
    if (lane == 0) out[0] = (float)v;
}

// ============================ launch ============================
extern "C" void kernel_launch(void* const* d_in, const int* in_sizes, int n_in,
                              void* d_out, int out_size)
{
    const float* em   = (const float*)d_in[0];   // (B,S,D)
    const int*   tags = (const int*)  d_in[1];   // (B,S)
    const float* mask = (const float*)d_in[2];   // (B,S)
    const float* W    = (const float*)d_in[3];   // (D,N)
    const float* bias = (const float*)d_in[4];   // (N,)
    const float* T    = (const float*)d_in[5];   // (N,N)
    float* out = (float*)d_out;                  // [loss, logits(B,S,33)]

    gemm_kernel <<<(Bn*Sn)/128, 64>>>(em, W, bias, out);
    scan_kernel <<<3*Bn, 32>>>(T, mask, tags, out);
    loss_kernel <<<1, 32>>>(out);
}